// round 4
// baseline (speedup 1.0000x reference)
#include <cuda_runtime.h>
#include <cuda_bf16.h>
#include <cstdint>

// GaussianBlur: 17-tap separable depthwise Gaussian (sigma=2), reflect_101,
// 32x3x512x512 fp32.  out = blur(x) + 254/255  (affine folded through blur).
//
// R3 -> R4 (was issue-slot bound: 75.5% issue, 36 scalar FFMA/output):
//  - packed fma.rn.f32x2 (Blackwell FFMA2): both passes compute 2 outputs per
//    instruction -> 8.5 FFMA2/output/pass instead of 17 FFMA.
//  - vertical pairs adjacent x columns: natural LDG.64 window, STS.64 out.
//  - horizontal pairs adjacent x outputs: even pairs free from LDS.128 quads,
//    odd pairs cost 2 MOV; stores stay contiguous STG.128.
//  - tap constants {k,k} as u64; symmetry dedups to 9 distinct pairs.

#define RAD   8
#define KS    17
#define IMGN  512
#define TW    128
#define TH    64
#define SW    (TW + 2 * RAD)        // 144
#define SWP   148                   // padded row stride (floats), %4==0
#define NTHR  288
#define VT    16                    // y outputs per vertical task
#define VWIN  (VT + 2 * RAD)        // 32-row window
#define NCOL2 (SW / 2)              // 72 float2 columns
#define HT    8                     // x outputs per horizontal task
#define HSEG  (TW / HT)             // 16
#define HTASKS (HSEG * TH)          // 1024

__device__ __forceinline__ constexpr float kg(int j) {
    constexpr float K[KS] = {
        6.6916291e-05f, 4.3634902e-04f, 2.2159845e-03f, 8.7641502e-03f,
        2.6995483e-02f, 6.4759664e-02f, 1.2098749e-01f, 1.7603573e-01f,
        1.9947065e-01f,
        1.7603573e-01f, 1.2098749e-01f, 6.4759664e-02f, 2.6995483e-02f,
        8.7641502e-03f, 2.2159845e-03f, 4.3634902e-04f, 6.6916291e-05f
    };
    return K[j];
}

// {k,k} packed into u64 (lane0 = low 32 bits). Folds at compile time.
__device__ __forceinline__ unsigned long long kk2(int j) {
    const unsigned int b = __float_as_uint(kg(j));
    return ((unsigned long long)b << 32) | b;
}

// packed acc += v * kk   (fma.rn.f32x2)
__device__ __forceinline__ void ffma2(float2& acc, float2 v,
                                      unsigned long long kk) {
    unsigned long long a, c;
    a = ((unsigned long long)__float_as_uint(v.y) << 32) | __float_as_uint(v.x);
    c = ((unsigned long long)__float_as_uint(acc.y) << 32) | __float_as_uint(acc.x);
    asm("fma.rn.f32x2 %0, %1, %2, %0;" : "+l"(c) : "l"(a), "l"(kk));
    acc.x = __uint_as_float((unsigned int)c);
    acc.y = __uint_as_float((unsigned int)(c >> 32));
}

__device__ __forceinline__ int mirror(int v) {
    // reflect_101, valid for |overhang| <= RAD
    const int a = ::abs(v);
    return ::min(a, 2 * (IMGN - 1) - a);
}

__global__ __launch_bounds__(NTHR, 3)
void gaussian_blur_fused(const float* __restrict__ in, float* __restrict__ out) {
    __shared__ __align__(16) float s_mid[TH * SWP];   // 64*148*4 = 37888 B

    const int x0 = blockIdx.x * TW;
    const int y0 = blockIdx.y * TH;
    const float* __restrict__ img  = in  + (size_t)blockIdx.z * (IMGN * IMGN);
    float*       __restrict__ oimg = out + (size_t)blockIdx.z * (IMGN * IMGN);
    const int tid = threadIdx.x;

    const bool interior = (x0 >= RAD) && (x0 + TW + RAD <= IMGN) &&
                          (y0 >= RAD) && (y0 + TH + RAD <= IMGN);

    // ---- vertical pass: 288 tasks, one per thread ----
    // task: one float2 column pair (2 adjacent x), VT consecutive y outputs.
    {
        const int c     = tid % NCOL2;      // 0..71
        const int strip = tid / NCOL2;      // 0..3
        const int yy    = y0 + strip * VT - RAD;

        float2 g[VWIN];
        if (interior) {
            const float2* __restrict__ p =
                (const float2*)(img + (size_t)yy * IMGN + (x0 - RAD)) + c;
            #pragma unroll
            for (int r = 0; r < VWIN; ++r)
                g[r] = p[r * (IMGN / 2)];            // LDG.64, immediate offsets
        } else {
            const int mx0 = mirror(x0 + 2 * c - RAD);
            const int mx1 = mirror(x0 + 2 * c - RAD + 1);
            #pragma unroll
            for (int r = 0; r < VWIN; ++r) {
                const int my = mirror(yy + r);
                g[r] = make_float2(img[(size_t)my * IMGN + mx0],
                                   img[(size_t)my * IMGN + mx1]);
            }
        }

        #pragma unroll
        for (int i = 0; i < VT; ++i) {
            float2 acc = make_float2(0.0f, 0.0f);
            #pragma unroll
            for (int j = 0; j < KS; ++j)
                ffma2(acc, g[i + j], kk2(j));
            *(float2*)(s_mid + (strip * VT + i) * SWP + 2 * c) = acc;
        }
    }
    __syncthreads();

    // ---- horizontal pass: row x 8-output segments, packed output pairs ----
    const float OFS = 254.0f / 255.0f;
    for (int t = tid; t < HTASKS; t += NTHR) {
        const int row = t >> 4;              // HSEG == 16
        const int seg = t & 15;

        // window m[0..23] via 6 aligned LDS.128
        const float4* __restrict__ src =
            (const float4*)(s_mid + row * SWP) + seg * 2;
        const float4 q0 = src[0], q1 = src[1], q2 = src[2],
                     q3 = src[3], q4 = src[4], q5 = src[5];
        const float m[HT + KS - 1] = {
            q0.x, q0.y, q0.z, q0.w,  q1.x, q1.y, q1.z, q1.w,
            q2.x, q2.y, q2.z, q2.w,  q3.x, q3.y, q3.z, q3.w,
            q4.x, q4.y, q4.z, q4.w,  q5.x, q5.y, q5.z, q5.w
        };

        float2 acc[HT / 2];
        #pragma unroll
        for (int i = 0; i < HT / 2; ++i) {
            acc[i] = make_float2(OFS, OFS);          // fold affine offset
            #pragma unroll
            for (int j = 0; j < KS; ++j)
                ffma2(acc[i], make_float2(m[2 * i + j], m[2 * i + j + 1]),
                      kk2(j));
        }

        float4* dst = (float4*)(oimg + (size_t)(y0 + row) * IMGN + x0 + seg * HT);
        dst[0] = make_float4(acc[0].x, acc[0].y, acc[1].x, acc[1].y);
        dst[1] = make_float4(acc[2].x, acc[2].y, acc[3].x, acc[3].y);
    }
}

extern "C" void kernel_launch(void* const* d_in, const int* in_sizes, int n_in,
                              void* d_out, int out_size) {
    const float* in = (const float*)d_in[0];
    float* out = (float*)d_out;
    const int n_imgs = in_sizes[0] / (IMGN * IMGN);   // 96
    dim3 grid(IMGN / TW, IMGN / TH, n_imgs);          // (4, 8, 96)
    gaussian_blur_fused<<<grid, NTHR>>>(in, out);
}